// round 2
// baseline (speedup 1.0000x reference)
#include <cuda_runtime.h>
#include <math.h>

// ---------------- problem constants ----------------
#define FEAT 1024
#define HID  256
#define NMAX 100000
#define KSAMP 8

// ---------------- device scratch (no runtime allocation allowed) ------------
__device__ float g_x[(size_t)NMAX * HID];   // relu(h @ W_fc^T + b)   [N,256]
__device__ float g_s[NMAX];                 // raw attention scores   [N]
__device__ float g_stats[2];                // {smax, Z}
__device__ int   g_ids[2 * KSAMP];          // top8 ids then bottom8 ids
__device__ float g_pool[HID];               // softmax-weighted pooled vector

// ---------------- zero init (graph replays need re-zero) --------------------
__global__ void zero_kernel(int N) {
    int i = blockIdx.x * 256 + threadIdx.x;
    if (i < N)   g_s[i] = 0.f;
    if (i < HID) g_pool[i] = 0.f;
}

// ---------------- GEMM1: x = relu(h @ W_fc^T + b_fc) ------------------------
// C[m,n] = sum_k h[m,k] * W[n,k],  M=N rows, N=256 cols, K=1024
// Tile 64x64x32, 256 threads, 4x4 microtile per thread.
__global__ void gemm_fc(const float* __restrict__ h, const float* __restrict__ W,
                        const float* __restrict__ b, int N) {
    __shared__ float As[32][64];  // h^T tile  (k, m)
    __shared__ float Bs[32][64];  // W^T tile  (k, n)
    const int m0 = blockIdx.x * 64;
    const int n0 = blockIdx.y * 64;
    const int tid = threadIdx.x;
    const int tn = tid & 15, tm = tid >> 4;

    float acc[4][4];
#pragma unroll
    for (int i = 0; i < 4; i++)
#pragma unroll
        for (int j = 0; j < 4; j++) acc[i][j] = 0.f;

    for (int k0 = 0; k0 < FEAT; k0 += 32) {
#pragma unroll
        for (int i = tid; i < 64 * 8; i += 256) {   // 64 rows x 8 float4
            int r = i >> 3, c4 = i & 7;
            int m = m0 + r;
            float4 v = make_float4(0.f, 0.f, 0.f, 0.f);
            if (m < N) v = *(const float4*)(h + (size_t)m * FEAT + k0 + c4 * 4);
            As[c4 * 4 + 0][r] = v.x; As[c4 * 4 + 1][r] = v.y;
            As[c4 * 4 + 2][r] = v.z; As[c4 * 4 + 3][r] = v.w;
        }
#pragma unroll
        for (int i = tid; i < 64 * 8; i += 256) {
            int r = i >> 3, c4 = i & 7;
            float4 v = *(const float4*)(W + (size_t)(n0 + r) * FEAT + k0 + c4 * 4);
            Bs[c4 * 4 + 0][r] = v.x; Bs[c4 * 4 + 1][r] = v.y;
            Bs[c4 * 4 + 2][r] = v.z; Bs[c4 * 4 + 3][r] = v.w;
        }
        __syncthreads();
#pragma unroll
        for (int k = 0; k < 32; k++) {
            float4 a = *(const float4*)&As[k][tm * 4];
            float4 w4 = *(const float4*)&Bs[k][tn * 4];
            acc[0][0] += a.x * w4.x; acc[0][1] += a.x * w4.y; acc[0][2] += a.x * w4.z; acc[0][3] += a.x * w4.w;
            acc[1][0] += a.y * w4.x; acc[1][1] += a.y * w4.y; acc[1][2] += a.y * w4.z; acc[1][3] += a.y * w4.w;
            acc[2][0] += a.z * w4.x; acc[2][1] += a.z * w4.y; acc[2][2] += a.z * w4.z; acc[2][3] += a.z * w4.w;
            acc[3][0] += a.w * w4.x; acc[3][1] += a.w * w4.y; acc[3][2] += a.w * w4.z; acc[3][3] += a.w * w4.w;
        }
        __syncthreads();
    }
#pragma unroll
    for (int i = 0; i < 4; i++) {
        int m = m0 + tm * 4 + i;
        if (m >= N) continue;
#pragma unroll
        for (int j = 0; j < 4; j++) {
            int n = n0 + tn * 4 + j;
            float v = acc[i][j] + b[n];
            g_x[(size_t)m * HID + n] = v > 0.f ? v : 0.f;
        }
    }
}

// ---------------- GEMM2: gated attention scores ------------------------------
// a = tanh(x@Wa^T + ba), g = sigmoid(x@Wb^T + bb), s[m] += sum_n a*g*Wc[n]
__global__ void gemm_attn(const float* __restrict__ Wa, const float* __restrict__ ba,
                          const float* __restrict__ Wb, const float* __restrict__ bbv,
                          const float* __restrict__ Wc, int N) {
    __shared__ float Xs[32][64];
    __shared__ float Was[32][64];
    __shared__ float Wbs[32][64];
    __shared__ float srow[64];
    const int m0 = blockIdx.x * 64;
    const int n0 = blockIdx.y * 64;
    const int tid = threadIdx.x;
    const int tn = tid & 15, tm = tid >> 4;

    float acca[4][4], accg[4][4];
#pragma unroll
    for (int i = 0; i < 4; i++)
#pragma unroll
        for (int j = 0; j < 4; j++) { acca[i][j] = 0.f; accg[i][j] = 0.f; }

    for (int k0 = 0; k0 < HID; k0 += 32) {
#pragma unroll
        for (int i = tid; i < 64 * 8; i += 256) {
            int r = i >> 3, c4 = i & 7;
            int m = m0 + r;
            float4 v = make_float4(0.f, 0.f, 0.f, 0.f);
            if (m < N) v = *(const float4*)(g_x + (size_t)m * HID + k0 + c4 * 4);
            Xs[c4 * 4 + 0][r] = v.x; Xs[c4 * 4 + 1][r] = v.y;
            Xs[c4 * 4 + 2][r] = v.z; Xs[c4 * 4 + 3][r] = v.w;
            float4 va = *(const float4*)(Wa + (size_t)(n0 + r) * HID + k0 + c4 * 4);
            Was[c4 * 4 + 0][r] = va.x; Was[c4 * 4 + 1][r] = va.y;
            Was[c4 * 4 + 2][r] = va.z; Was[c4 * 4 + 3][r] = va.w;
            float4 vb = *(const float4*)(Wb + (size_t)(n0 + r) * HID + k0 + c4 * 4);
            Wbs[c4 * 4 + 0][r] = vb.x; Wbs[c4 * 4 + 1][r] = vb.y;
            Wbs[c4 * 4 + 2][r] = vb.z; Wbs[c4 * 4 + 3][r] = vb.w;
        }
        __syncthreads();
#pragma unroll
        for (int k = 0; k < 32; k++) {
            float4 xv = *(const float4*)&Xs[k][tm * 4];
            float4 wa = *(const float4*)&Was[k][tn * 4];
            float4 wb = *(const float4*)&Wbs[k][tn * 4];
            acca[0][0] += xv.x * wa.x; acca[0][1] += xv.x * wa.y; acca[0][2] += xv.x * wa.z; acca[0][3] += xv.x * wa.w;
            acca[1][0] += xv.y * wa.x; acca[1][1] += xv.y * wa.y; acca[1][2] += xv.y * wa.z; acca[1][3] += xv.y * wa.w;
            acca[2][0] += xv.z * wa.x; acca[2][1] += xv.z * wa.y; acca[2][2] += xv.z * wa.z; acca[2][3] += xv.z * wa.w;
            acca[3][0] += xv.w * wa.x; acca[3][1] += xv.w * wa.y; acca[3][2] += xv.w * wa.z; acca[3][3] += xv.w * wa.w;
            accg[0][0] += xv.x * wb.x; accg[0][1] += xv.x * wb.y; accg[0][2] += xv.x * wb.z; accg[0][3] += xv.x * wb.w;
            accg[1][0] += xv.y * wb.x; accg[1][1] += xv.y * wb.y; accg[1][2] += xv.y * wb.z; accg[1][3] += xv.y * wb.w;
            accg[2][0] += xv.z * wb.x; accg[2][1] += xv.z * wb.y; accg[2][2] += xv.z * wb.z; accg[2][3] += xv.z * wb.w;
            accg[3][0] += xv.w * wb.x; accg[3][1] += xv.w * wb.y; accg[3][2] += xv.w * wb.z; accg[3][3] += xv.w * wb.w;
        }
        __syncthreads();
    }

    if (tid < 64) srow[tid] = 0.f;
    __syncthreads();
#pragma unroll
    for (int i = 0; i < 4; i++) {
        float part = 0.f;
#pragma unroll
        for (int j = 0; j < 4; j++) {
            int n = n0 + tn * 4 + j;
            float c1 = acca[i][j] + ba[n];
            float c2 = accg[i][j] + bbv[n];
            float t = tanhf(c1);
            float sg = 1.f / (1.f + expf(-c2));
            part += t * sg * Wc[n];
        }
        atomicAdd(&srow[tm * 4 + i], part);
    }
    __syncthreads();
    if (tid < 64) {
        int m = m0 + tid;
        if (m < N) atomicAdd(&g_s[m], srow[tid]);
    }
}

// ---------------- reduction: max, top/bottom-8, sumexp ----------------------
__device__ __forceinline__ bool better_top(float v1, int i1, float v2, int i2) {
    return (v1 > v2) || (v1 == v2 && i1 < i2);
}
__device__ __forceinline__ bool better_bot(float v1, int i1, float v2, int i2) {
    return (v1 < v2) || (v1 == v2 && i1 < i2);
}

__global__ void reduce_kernel(int N) {
    __shared__ float red[256];
    __shared__ float candv[2][64 * KSAMP];
    __shared__ int   candi[2][64 * KSAMP];
    const int t = threadIdx.x;

    // pass 1: max
    float mx = -INFINITY;
    for (int i = t; i < N; i += 256) mx = fmaxf(mx, g_s[i]);
    red[t] = mx; __syncthreads();
    for (int o = 128; o > 0; o >>= 1) {
        if (t < o) red[t] = fmaxf(red[t], red[t + o]);
        __syncthreads();
    }
    float smax = red[0];
    __syncthreads();

    // pass 2: per-thread top8/bottom8 candidates (64 scanning threads)
    if (t < 64) {
        float tv[KSAMP], bv[KSAMP];
        int   ti[KSAMP], bi[KSAMP];
#pragma unroll
        for (int q = 0; q < KSAMP; q++) {
            tv[q] = -INFINITY; ti[q] = 0x7fffffff;
            bv[q] =  INFINITY; bi[q] = 0x7fffffff;
        }
        for (int i = t; i < N; i += 64) {
            float v = g_s[i];
            if (better_top(v, i, tv[KSAMP - 1], ti[KSAMP - 1])) {
                tv[KSAMP - 1] = v; ti[KSAMP - 1] = i;
#pragma unroll
                for (int q = KSAMP - 1; q > 0; q--) {
                    if (better_top(tv[q], ti[q], tv[q - 1], ti[q - 1])) {
                        float fv = tv[q]; tv[q] = tv[q - 1]; tv[q - 1] = fv;
                        int iv = ti[q]; ti[q] = ti[q - 1]; ti[q - 1] = iv;
                    }
                }
            }
            if (better_bot(v, i, bv[KSAMP - 1], bi[KSAMP - 1])) {
                bv[KSAMP - 1] = v; bi[KSAMP - 1] = i;
#pragma unroll
                for (int q = KSAMP - 1; q > 0; q--) {
                    if (better_bot(bv[q], bi[q], bv[q - 1], bi[q - 1])) {
                        float fv = bv[q]; bv[q] = bv[q - 1]; bv[q - 1] = fv;
                        int iv = bi[q]; bi[q] = bi[q - 1]; bi[q - 1] = iv;
                    }
                }
            }
        }
#pragma unroll
        for (int q = 0; q < KSAMP; q++) {
            candv[0][t * KSAMP + q] = tv[q]; candi[0][t * KSAMP + q] = ti[q];
            candv[1][t * KSAMP + q] = bv[q]; candi[1][t * KSAMP + q] = bi[q];
        }
    }
    __syncthreads();

    // merge by threads 0 (top) and 1 (bottom)
    if (t == 0) {
        float tv[KSAMP]; int ti[KSAMP];
#pragma unroll
        for (int q = 0; q < KSAMP; q++) { tv[q] = -INFINITY; ti[q] = 0x7fffffff; }
        for (int c = 0; c < 64 * KSAMP; c++) {
            float v = candv[0][c]; int i = candi[0][c];
            if (better_top(v, i, tv[KSAMP - 1], ti[KSAMP - 1])) {
                tv[KSAMP - 1] = v; ti[KSAMP - 1] = i;
#pragma unroll
                for (int q = KSAMP - 1; q > 0; q--) {
                    if (better_top(tv[q], ti[q], tv[q - 1], ti[q - 1])) {
                        float fv = tv[q]; tv[q] = tv[q - 1]; tv[q - 1] = fv;
                        int iv = ti[q]; ti[q] = ti[q - 1]; ti[q - 1] = iv;
                    }
                }
            }
        }
#pragma unroll
        for (int q = 0; q < KSAMP; q++) g_ids[q] = ti[q];
    }
    if (t == 1) {
        float bvv[KSAMP]; int bii[KSAMP];
#pragma unroll
        for (int q = 0; q < KSAMP; q++) { bvv[q] = INFINITY; bii[q] = 0x7fffffff; }
        for (int c = 0; c < 64 * KSAMP; c++) {
            float v = candv[1][c]; int i = candi[1][c];
            if (better_bot(v, i, bvv[KSAMP - 1], bii[KSAMP - 1])) {
                bvv[KSAMP - 1] = v; bii[KSAMP - 1] = i;
#pragma unroll
                for (int q = KSAMP - 1; q > 0; q--) {
                    if (better_bot(bvv[q], bii[q], bvv[q - 1], bii[q - 1])) {
                        float fv = bvv[q]; bvv[q] = bvv[q - 1]; bvv[q - 1] = fv;
                        int iv = bii[q]; bii[q] = bii[q - 1]; bii[q - 1] = iv;
                    }
                }
            }
        }
#pragma unroll
        for (int q = 0; q < KSAMP; q++) g_ids[KSAMP + q] = bii[q];
    }

    // pass 3: sum of exp
    float se = 0.f;
    for (int i = t; i < N; i += 256) se += expf(g_s[i] - smax);
    __syncthreads();
    red[t] = se; __syncthreads();
    for (int o = 128; o > 0; o >>= 1) {
        if (t < o) red[t] += red[t + o];
        __syncthreads();
    }
    if (t == 0) { g_stats[0] = smax; g_stats[1] = red[0]; }
}

// ---------------- attention pooling: M = softmax(s) @ x ----------------------
__global__ void pool_kernel(int N) {
    __shared__ float sw[256];
    const int t = threadIdx.x;
    const int m0 = blockIdx.x * 256;
    float smax = g_stats[0];
    float invZ = 1.f / g_stats[1];
    int m = m0 + t;
    sw[t] = (m < N) ? expf(g_s[m] - smax) * invZ : 0.f;
    __syncthreads();
    float acc = 0.f;
    int lim = min(256, N - m0);
    for (int r = 0; r < lim; r++) acc += sw[r] * g_x[(size_t)(m0 + r) * HID + t];
    atomicAdd(&g_pool[t], acc);
}

// ---------------- final heads ------------------------------------------------
__device__ __forceinline__ float block_reduce(float v, float* red, int t) {
    red[t] = v; __syncthreads();
    for (int o = 128; o > 0; o >>= 1) {
        if (t < o) red[t] += red[t + o];
        __syncthreads();
    }
    float r = red[0]; __syncthreads();
    return r;
}

__global__ void final_kernel(const float* __restrict__ Wcls, const float* __restrict__ bcls,
                             const float* __restrict__ Winst, const float* __restrict__ binst,
                             const int* __restrict__ label, float* __restrict__ out, int out_size) {
    __shared__ float red[256];
    const int t = threadIdx.x;
    float Mv = g_pool[t];

    float l0 = block_reduce(Mv * Wcls[t], red, t) + bcls[0];
    float l1 = block_reduce(Mv * Wcls[HID + t], red, t) + bcls[1];

    float mx = fmaxf(l0, l1);
    float e0 = expf(l0 - mx), e1 = expf(l1 - mx);
    float inv = 1.f / (e0 + e1);
    float p0 = e0 * inv, p1 = e1 * inv;
    int yhat = (l1 > l0) ? 1 : 0;

    int lab = label[0];
    float total = 0.f;
    for (int i = 0; i < 2; i++) {
        float w = (lab == i) ? 1.f : 0.f;
        float lsum = 0.f;
        for (int j = 0; j < 2 * KSAMP; j++) {
            int id = g_ids[j];
            float xv = g_x[(size_t)id * HID + t];
            float s0 = block_reduce(xv * Winst[(size_t)(i * 2 + 0) * HID + t], red, t) + binst[i * 2 + 0];
            float s1 = block_reduce(xv * Winst[(size_t)(i * 2 + 1) * HID + t], red, t) + binst[i * 2 + 1];
            int tgt = (j < KSAMP) ? 1 : 0;
            // delta = alpha*(1-onehot), alpha=1, tau=1
            float a0 = s0 + ((tgt == 0) ? 0.f : 1.f);
            float a1 = s1 + ((tgt == 1) ? 0.f : 1.f);
            float mm = fmaxf(a0, a1);
            float lse = mm + logf(expf(a0 - mm) + expf(a1 - mm));
            float sy = (tgt == 1) ? s1 : s0;
            lsum += lse - sy;
        }
        total += w * (lsum * (1.f / (2.f * KSAMP)));
    }

    if (t == 0) {
        if (out_size > 0) out[0] = l0;
        if (out_size > 1) out[1] = l1;
        if (out_size > 2) out[2] = p0;
        if (out_size > 3) out[3] = p1;
        if (out_size > 4) out[4] = (float)yhat;
        if (out_size > 5) out[5] = total;
    }
}

// ---------------- launcher ---------------------------------------------------
extern "C" void kernel_launch(void* const* d_in, const int* in_sizes, int n_in,
                              void* d_out, int out_size) {
    const float* h     = (const float*)d_in[0];
    const int*   label = (const int*)d_in[1];
    const float* W_fc  = (const float*)d_in[2];
    const float* b_fc  = (const float*)d_in[3];
    const float* Wa    = (const float*)d_in[4];
    const float* ba    = (const float*)d_in[5];
    const float* Wb    = (const float*)d_in[6];
    const float* bb    = (const float*)d_in[7];
    const float* Wc    = (const float*)d_in[8];
    // d_in[9] = bc : softmax/top-k shift-invariant, mathematically unused
    const float* W_cls  = (const float*)d_in[10];
    const float* b_cls  = (const float*)d_in[11];
    const float* W_inst = (const float*)d_in[12];
    const float* b_inst = (const float*)d_in[13];

    int N = in_sizes[0] / FEAT;
    if (N > NMAX) N = NMAX;
    int mb = (N + 63) / 64;

    zero_kernel<<<(N + 255) / 256, 256>>>(N);
    gemm_fc<<<dim3(mb, 4), 256>>>(h, W_fc, b_fc, N);
    gemm_attn<<<dim3(mb, 4), 256>>>(Wa, ba, Wb, bb, Wc, N);
    reduce_kernel<<<1, 256>>>(N);
    pool_kernel<<<(N + 255) / 256, 256>>>(N);
    final_kernel<<<1, 256>>>(W_cls, b_cls, W_inst, b_inst, label, (float*)d_out, out_size);
}

// round 4
// speedup vs baseline: 1.6176x; 1.6176x over previous
#include <cuda_runtime.h>
#include <math.h>

// ---------------- problem constants ----------------
#define FEAT 1024
#define HID  256
#define NMAX 100000
#define KSAMP 8
#define R2B  64      // blocks in candidate/sumexp pass

typedef unsigned long long u64;
typedef unsigned int u32;

// ---------------- device scratch ----------------
__device__ float g_x[(size_t)NMAX * HID];   // relu(h @ W_fc^T + b)   [N,256]
__device__ float g_s[NMAX];                 // raw attention scores   [N]
__device__ u32   g_smax_u;                  // encoded max
__device__ float g_Z;                       // sum exp
__device__ int   g_ids[2 * KSAMP];          // top8 ids then bottom8 ids
__device__ float g_pool[HID];               // pooled vector
__device__ float g_candv[2][R2B * KSAMP];
__device__ int   g_candi[2][R2B * KSAMP];

// ---------------- f32x2 helpers ----------------
__device__ __forceinline__ void fma2(u64 &d, u64 a, u64 b) {
    asm("fma.rn.f32x2 %0, %1, %2, %0;" : "+l"(d) : "l"(a), "l"(b));
}
__device__ __forceinline__ u64 pack2(float lo, float hi) {
    u64 r; asm("mov.b64 %0, {%1, %2};" : "=l"(r) : "f"(lo), "f"(hi)); return r;
}
__device__ __forceinline__ float2 unpack2(u64 v) {
    float2 r; asm("mov.b64 {%0, %1}, %2;" : "=f"(r.x), "=f"(r.y) : "l"(v)); return r;
}

// monotonic float<->uint encoding for atomicMax
__device__ __forceinline__ u32 enc_max(float f) {
    u32 u = __float_as_uint(f);
    return (u & 0x80000000u) ? ~u : (u | 0x80000000u);
}
__device__ __forceinline__ float dec_max(u32 u) {
    return __uint_as_float((u & 0x80000000u) ? (u & 0x7FFFFFFFu) : ~u);
}

// ---------------- zero init (graph replays) ----------------
__global__ void zero_kernel(int N) {
    int i = blockIdx.x * 256 + threadIdx.x;
    if (i < N)   g_s[i] = 0.f;
    if (i < HID) g_pool[i] = 0.f;
    if (blockIdx.x == 0 && threadIdx.x == 0) { g_smax_u = 0u; g_Z = 0.f; }
}

// ---------------- GEMM1: x = relu(h @ W_fc^T + b_fc) ------------------------
// block tile 128(m) x 128(n), K-step 16, 256 threads, 8x8 microtile (f32x2)
__global__ __launch_bounds__(256) void gemm_fc(
        const float* __restrict__ h, const float* __restrict__ W,
        const float* __restrict__ b, int N) {
    __shared__ float As[16][128];
    __shared__ float Bs[16][128];
    const int m0 = blockIdx.x * 128;
    const int n0 = blockIdx.y * 128;
    const int tid = threadIdx.x;
    const int tn = tid & 15, tm = tid >> 4;
    const int lr = tid >> 1;
    const int lc = (tid & 1) << 3;

    u64 acc[4][8];
#pragma unroll
    for (int i = 0; i < 4; i++)
#pragma unroll
        for (int j = 0; j < 8; j++) acc[i][j] = 0ull;

    for (int k0 = 0; k0 < FEAT; k0 += 16) {
        float4 a0, a1;
        int m = m0 + lr;
        if (m < N) {
            const float* p = h + (size_t)m * FEAT + k0 + lc;
            a0 = *(const float4*)p; a1 = *(const float4*)(p + 4);
        } else {
            a0 = make_float4(0.f,0.f,0.f,0.f); a1 = a0;
        }
        As[lc+0][lr]=a0.x; As[lc+1][lr]=a0.y; As[lc+2][lr]=a0.z; As[lc+3][lr]=a0.w;
        As[lc+4][lr]=a1.x; As[lc+5][lr]=a1.y; As[lc+6][lr]=a1.z; As[lc+7][lr]=a1.w;
        const float* q = W + (size_t)(n0 + lr) * FEAT + k0 + lc;
        float4 b0 = *(const float4*)q, b1 = *(const float4*)(q + 4);
        Bs[lc+0][lr]=b0.x; Bs[lc+1][lr]=b0.y; Bs[lc+2][lr]=b0.z; Bs[lc+3][lr]=b0.w;
        Bs[lc+4][lr]=b1.x; Bs[lc+5][lr]=b1.y; Bs[lc+6][lr]=b1.z; Bs[lc+7][lr]=b1.w;
        __syncthreads();
#pragma unroll
        for (int k = 0; k < 16; k++) {
            const float4 x0 = *(const float4*)&As[k][tm*8];
            const float4 x1 = *(const float4*)&As[k][tm*8+4];
            u64 ap0 = pack2(x0.x, x0.y), ap1 = pack2(x0.z, x0.w);
            u64 ap2 = pack2(x1.x, x1.y), ap3 = pack2(x1.z, x1.w);
            const float4 w0 = *(const float4*)&Bs[k][tn*8];
            const float4 w1 = *(const float4*)&Bs[k][tn*8+4];
            float wv[8] = {w0.x,w0.y,w0.z,w0.w,w1.x,w1.y,w1.z,w1.w};
#pragma unroll
            for (int j = 0; j < 8; j++) {
                u64 wd = pack2(wv[j], wv[j]);
                fma2(acc[0][j], ap0, wd);
                fma2(acc[1][j], ap1, wd);
                fma2(acc[2][j], ap2, wd);
                fma2(acc[3][j], ap3, wd);
            }
        }
        __syncthreads();
    }
#pragma unroll
    for (int i = 0; i < 4; i++) {
        int mlo = m0 + tm*8 + i*2;
#pragma unroll
        for (int j = 0; j < 8; j++) {
            int n = n0 + tn*8 + j;
            float2 v = unpack2(acc[i][j]);
            float bj = b[n];
            if (mlo < N)     g_x[(size_t)mlo * HID + n]     = fmaxf(v.x + bj, 0.f);
            if (mlo + 1 < N) g_x[(size_t)(mlo+1) * HID + n] = fmaxf(v.y + bj, 0.f);
        }
    }
}

// ---------------- GEMM2: gated attention scores ------------------------------
// block: 128 m-rows x (64 tanh-cols + 64 sigmoid-cols), D_ATT split in 4 y-blocks
__global__ __launch_bounds__(256) void gemm_attn(
        const float* __restrict__ Wa, const float* __restrict__ ba,
        const float* __restrict__ Wb, const float* __restrict__ bbv,
        const float* __restrict__ Wc, int N) {
    __shared__ float Xs[16][128];
    __shared__ float Bs[16][128];   // cols 0..63 Wa rows, 64..127 Wb rows
    __shared__ float srow[128];
    const int m0 = blockIdx.x * 128;
    const int n0 = blockIdx.y * 64;     // attention-dim offset
    const int tid = threadIdx.x;
    const int tn = tid & 15, tm = tid >> 4;
    const int lr = tid >> 1;
    const int lc = (tid & 1) << 3;

    u64 acc_a[4][4], acc_g[4][4];
#pragma unroll
    for (int i = 0; i < 4; i++)
#pragma unroll
        for (int j = 0; j < 4; j++) { acc_a[i][j] = 0ull; acc_g[i][j] = 0ull; }

    for (int k0 = 0; k0 < HID; k0 += 16) {
        float4 a0, a1;
        int m = m0 + lr;
        if (m < N) {
            const float* p = g_x + (size_t)m * HID + k0 + lc;
            a0 = *(const float4*)p; a1 = *(const float4*)(p + 4);
        } else {
            a0 = make_float4(0.f,0.f,0.f,0.f); a1 = a0;
        }
        Xs[lc+0][lr]=a0.x; Xs[lc+1][lr]=a0.y; Xs[lc+2][lr]=a0.z; Xs[lc+3][lr]=a0.w;
        Xs[lc+4][lr]=a1.x; Xs[lc+5][lr]=a1.y; Xs[lc+6][lr]=a1.z; Xs[lc+7][lr]=a1.w;
        const float* wrow = (lr < 64) ? (Wa + (size_t)(n0 + lr) * HID)
                                      : (Wb + (size_t)(n0 + lr - 64) * HID);
        const float* q = wrow + k0 + lc;
        float4 b0 = *(const float4*)q, b1 = *(const float4*)(q + 4);
        Bs[lc+0][lr]=b0.x; Bs[lc+1][lr]=b0.y; Bs[lc+2][lr]=b0.z; Bs[lc+3][lr]=b0.w;
        Bs[lc+4][lr]=b1.x; Bs[lc+5][lr]=b1.y; Bs[lc+6][lr]=b1.z; Bs[lc+7][lr]=b1.w;
        __syncthreads();
#pragma unroll
        for (int k = 0; k < 16; k++) {
            const float4 x0 = *(const float4*)&Xs[k][tm*8];
            const float4 x1 = *(const float4*)&Xs[k][tm*8+4];
            u64 ap0 = pack2(x0.x, x0.y), ap1 = pack2(x0.z, x0.w);
            u64 ap2 = pack2(x1.x, x1.y), ap3 = pack2(x1.z, x1.w);
            const float4 wa = *(const float4*)&Bs[k][tn*4];
            const float4 wg = *(const float4*)&Bs[k][64 + tn*4];
            float wav[4] = {wa.x, wa.y, wa.z, wa.w};
            float wgv[4] = {wg.x, wg.y, wg.z, wg.w};
#pragma unroll
            for (int j = 0; j < 4; j++) {
                u64 wd = pack2(wav[j], wav[j]);
                fma2(acc_a[0][j], ap0, wd); fma2(acc_a[1][j], ap1, wd);
                fma2(acc_a[2][j], ap2, wd); fma2(acc_a[3][j], ap3, wd);
                u64 wd2 = pack2(wgv[j], wgv[j]);
                fma2(acc_g[0][j], ap0, wd2); fma2(acc_g[1][j], ap1, wd2);
                fma2(acc_g[2][j], ap2, wd2); fma2(acc_g[3][j], ap3, wd2);
            }
        }
        __syncthreads();
    }

    if (tid < 128) srow[tid] = 0.f;
    __syncthreads();
    float part[8];
#pragma unroll
    for (int r = 0; r < 8; r++) part[r] = 0.f;
#pragma unroll
    for (int i = 0; i < 4; i++) {
#pragma unroll
        for (int j = 0; j < 4; j++) {
            int nn = n0 + tn*4 + j;
            float bav = ba[nn], bgv = bbv[nn], wc = Wc[nn];
            float2 va = unpack2(acc_a[i][j]);
            float2 vg = unpack2(acc_g[i][j]);
            part[i*2+0] += tanhf(va.x + bav) * (1.f/(1.f+expf(-(vg.x + bgv)))) * wc;
            part[i*2+1] += tanhf(va.y + bav) * (1.f/(1.f+expf(-(vg.y + bgv)))) * wc;
        }
    }
#pragma unroll
    for (int r = 0; r < 8; r++) atomicAdd(&srow[tm*8 + r], part[r]);
    __syncthreads();
    if (tid < 128) {
        int m = m0 + tid;
        if (m < N) atomicAdd(&g_s[m], srow[tid]);
    }
}

// ---------------- top/bottom-8 insert helpers ----------------
__device__ __forceinline__ bool better_top(float v1, int i1, float v2, int i2) {
    return (v1 > v2) || (v1 == v2 && i1 < i2);
}
__device__ __forceinline__ bool better_bot(float v1, int i1, float v2, int i2) {
    return (v1 < v2) || (v1 == v2 && i1 < i2);
}
__device__ __forceinline__ void ins_top(float v, int i, float* tv, int* ti) {
    if (better_top(v, i, tv[KSAMP-1], ti[KSAMP-1])) {
        tv[KSAMP-1] = v; ti[KSAMP-1] = i;
#pragma unroll
        for (int q = KSAMP-1; q > 0; q--)
            if (better_top(tv[q], ti[q], tv[q-1], ti[q-1])) {
                float fv = tv[q]; tv[q] = tv[q-1]; tv[q-1] = fv;
                int iv = ti[q]; ti[q] = ti[q-1]; ti[q-1] = iv;
            }
    }
}
__device__ __forceinline__ void ins_bot(float v, int i, float* bv, int* bi) {
    if (better_bot(v, i, bv[KSAMP-1], bi[KSAMP-1])) {
        bv[KSAMP-1] = v; bi[KSAMP-1] = i;
#pragma unroll
        for (int q = KSAMP-1; q > 0; q--)
            if (better_bot(bv[q], bi[q], bv[q-1], bi[q-1])) {
                float fv = bv[q]; bv[q] = bv[q-1]; bv[q-1] = fv;
                int iv = bi[q]; bi[q] = bi[q-1]; bi[q-1] = iv;
            }
    }
}

// ---------------- R1: global max ----------------
__global__ void reduce_max(int N) {
    __shared__ float red[256];
    int t = threadIdx.x;
    float mx = -INFINITY;
    for (int i = blockIdx.x * 256 + t; i < N; i += gridDim.x * 256)
        mx = fmaxf(mx, g_s[i]);
    red[t] = mx; __syncthreads();
    for (int o = 128; o > 0; o >>= 1) {
        if (t < o) red[t] = fmaxf(red[t], red[t + o]);
        __syncthreads();
    }
    if (t == 0) atomicMax(&g_smax_u, enc_max(red[0]));
}

// ---------------- R2: sum-exp + per-block top/bottom-8 candidates ----------
__global__ void reduce_cand(int N) {
    __shared__ float red[256];
    __shared__ float cv[2][256 * KSAMP];
    __shared__ int   ci[2][256 * KSAMP];
    __shared__ float mv[2][32 * KSAMP];
    __shared__ int   mi[2][32 * KSAMP];
    int t = threadIdx.x;
    float smax = dec_max(g_smax_u);

    float tv[KSAMP], bv[KSAMP];
    int   ti[KSAMP], bi[KSAMP];
#pragma unroll
    for (int q = 0; q < KSAMP; q++) {
        tv[q] = -INFINITY; ti[q] = 0x7fffffff;
        bv[q] =  INFINITY; bi[q] = 0x7fffffff;
    }
    float se = 0.f;
    for (int i = blockIdx.x * 256 + t; i < N; i += R2B * 256) {
        float v = g_s[i];
        se += expf(v - smax);
        ins_top(v, i, tv, ti);
        ins_bot(v, i, bv, bi);
    }
    red[t] = se;
#pragma unroll
    for (int q = 0; q < KSAMP; q++) {
        cv[0][t*KSAMP + q] = tv[q]; ci[0][t*KSAMP + q] = ti[q];
        cv[1][t*KSAMP + q] = bv[q]; ci[1][t*KSAMP + q] = bi[q];
    }
    __syncthreads();
    // sum reduce
    for (int o = 128; o > 0; o >>= 1) {
        if (t < o) red[t] += red[t + o];
        __syncthreads();
    }
    if (t == 0) atomicAdd(&g_Z, red[0]);

    // lane-level merge: tids 0..31 top, 32..63 bottom; each covers 64 entries
    if (t < 64) {
        int dir = t >> 5;
        int lane = t & 31;
        float lv[KSAMP]; int li[KSAMP];
#pragma unroll
        for (int q = 0; q < KSAMP; q++) {
            lv[q] = dir ? INFINITY : -INFINITY; li[q] = 0x7fffffff;
        }
        for (int c = lane * 64; c < lane * 64 + 64; c++) {
            float v = cv[dir][c]; int i = ci[dir][c];
            if (dir == 0) ins_top(v, i, lv, li); else ins_bot(v, i, lv, li);
        }
#pragma unroll
        for (int q = 0; q < KSAMP; q++) { mv[dir][lane*KSAMP+q] = lv[q]; mi[dir][lane*KSAMP+q] = li[q]; }
    }
    __syncthreads();
    // block-level merge by threads 0 (top) and 1 (bottom)
    if (t < 2) {
        int dir = t;
        float lv[KSAMP]; int li[KSAMP];
#pragma unroll
        for (int q = 0; q < KSAMP; q++) {
            lv[q] = dir ? INFINITY : -INFINITY; li[q] = 0x7fffffff;
        }
        for (int c = 0; c < 32 * KSAMP; c++) {
            float v = mv[dir][c]; int i = mi[dir][c];
            if (dir == 0) ins_top(v, i, lv, li); else ins_bot(v, i, lv, li);
        }
#pragma unroll
        for (int q = 0; q < KSAMP; q++) {
            g_candv[dir][blockIdx.x * KSAMP + q] = lv[q];
            g_candi[dir][blockIdx.x * KSAMP + q] = li[q];
        }
    }
}

// ---------------- R3: final candidate merge ----------------
__global__ void reduce_merge() {
    int t = threadIdx.x;
    if (t < 2) {
        int dir = t;
        float lv[KSAMP]; int li[KSAMP];
#pragma unroll
        for (int q = 0; q < KSAMP; q++) {
            lv[q] = dir ? INFINITY : -INFINITY; li[q] = 0x7fffffff;
        }
        for (int c = 0; c < R2B * KSAMP; c++) {
            float v = g_candv[dir][c]; int i = g_candi[dir][c];
            if (dir == 0) ins_top(v, i, lv, li); else ins_bot(v, i, lv, li);
        }
#pragma unroll
        for (int q = 0; q < KSAMP; q++) g_ids[dir * KSAMP + q] = li[q];
    }
}

// ---------------- attention pooling: M = softmax(s) @ x ----------------------
__global__ void pool_kernel(int N) {
    __shared__ float sw[256];
    const int t = threadIdx.x;
    const int m0 = blockIdx.x * 256;
    float smax = dec_max(g_smax_u);
    float invZ = 1.f / g_Z;
    int m = m0 + t;
    sw[t] = (m < N) ? expf(g_s[m] - smax) * invZ : 0.f;
    __syncthreads();
    float acc = 0.f;
    int lim = min(256, N - m0);
    for (int r = 0; r < lim; r++) acc += sw[r] * g_x[(size_t)(m0 + r) * HID + t];
    atomicAdd(&g_pool[t], acc);
}

// ---------------- final heads ------------------------------------------------
__device__ __forceinline__ float block_reduce(float v, float* red, int t) {
    red[t] = v; __syncthreads();
    for (int o = 128; o > 0; o >>= 1) {
        if (t < o) red[t] += red[t + o];
        __syncthreads();
    }
    float r = red[0]; __syncthreads();
    return r;
}

__global__ void final_kernel(const float* __restrict__ Wcls, const float* __restrict__ bcls,
                             const float* __restrict__ Winst, const float* __restrict__ binst,
                             const int* __restrict__ label, float* __restrict__ out, int out_size) {
    __shared__ float red[256];
    const int t = threadIdx.x;
    float Mv = g_pool[t];

    float l0 = block_reduce(Mv * Wcls[t], red, t) + bcls[0];
    float l1 = block_reduce(Mv * Wcls[HID + t], red, t) + bcls[1];

    float mx = fmaxf(l0, l1);
    float e0 = expf(l0 - mx), e1 = expf(l1 - mx);
    float inv = 1.f / (e0 + e1);
    float p0 = e0 * inv, p1 = e1 * inv;
    int yhat = (l1 > l0) ? 1 : 0;

    int lab = label[0];
    float total = 0.f;
    for (int i = 0; i < 2; i++) {
        float w = (lab == i) ? 1.f : 0.f;
        float lsum = 0.f;
        for (int j = 0; j < 2 * KSAMP; j++) {
            int id = g_ids[j];
            float xv = g_x[(size_t)id * HID + t];
            float s0 = block_reduce(xv * Winst[(size_t)(i * 2 + 0) * HID + t], red, t) + binst[i * 2 + 0];
            float s1 = block_reduce(xv * Winst[(size_t)(i * 2 + 1) * HID + t], red, t) + binst[i * 2 + 1];
            int tgt = (j < KSAMP) ? 1 : 0;
            float a0 = s0 + ((tgt == 0) ? 0.f : 1.f);
            float a1 = s1 + ((tgt == 1) ? 0.f : 1.f);
            float mm = fmaxf(a0, a1);
            float lse = mm + logf(expf(a0 - mm) + expf(a1 - mm));
            float sy = (tgt == 1) ? s1 : s0;
            lsum += lse - sy;
        }
        total += w * (lsum * (1.f / (2.f * KSAMP)));
    }

    if (t == 0) {
        if (out_size > 0) out[0] = l0;
        if (out_size > 1) out[1] = l1;
        if (out_size > 2) out[2] = p0;
        if (out_size > 3) out[3] = p1;
        if (out_size > 4) out[4] = (float)yhat;
        if (out_size > 5) out[5] = total;
    }
}

// ---------------- launcher ---------------------------------------------------
extern "C" void kernel_launch(void* const* d_in, const int* in_sizes, int n_in,
                              void* d_out, int out_size) {
    const float* h     = (const float*)d_in[0];
    const int*   label = (const int*)d_in[1];
    const float* W_fc  = (const float*)d_in[2];
    const float* b_fc  = (const float*)d_in[3];
    const float* Wa    = (const float*)d_in[4];
    const float* ba    = (const float*)d_in[5];
    const float* Wb    = (const float*)d_in[6];
    const float* bb    = (const float*)d_in[7];
    const float* Wc    = (const float*)d_in[8];
    // d_in[9] = bc : softmax/top-k shift-invariant, mathematically unused
    const float* W_cls  = (const float*)d_in[10];
    const float* b_cls  = (const float*)d_in[11];
    const float* W_inst = (const float*)d_in[12];
    const float* b_inst = (const float*)d_in[13];

    int N = in_sizes[0] / FEAT;
    if (N > NMAX) N = NMAX;
    int mb = (N + 127) / 128;

    zero_kernel<<<(N + 255) / 256, 256>>>(N);
    gemm_fc<<<dim3(mb, 2), 256>>>(h, W_fc, b_fc, N);
    gemm_attn<<<dim3(mb, 4), 256>>>(Wa, ba, Wb, bb, Wc, N);
    reduce_max<<<128, 256>>>(N);
    reduce_cand<<<R2B, 256>>>(N);
    reduce_merge<<<1, 32>>>();
    pool_kernel<<<(N + 255) / 256, 256>>>(N);
    final_kernel<<<1, 256>>>(W_cls, b_cls, W_inst, b_inst, label, (float*)d_out, out_size);
}